// round 11
// baseline (speedup 1.0000x reference)
#include <cuda_runtime.h>
#include <math.h>

#define W 512
#define H 512
#define PLANE (W * H)

// hcK = 0.5 * cos(K*pi/16), float32 of the exact float64 values
#define HC1 0.4903926402016152f
#define HC2 0.4619397662556434f
#define HC3 0.4157348061512726f
#define HC4 0.3535533905932738f
#define HC5 0.2777851165098011f
#define HC6 0.1913417161825449f
#define HC7 0.0975451610080641f

__constant__ int LUMi[64] = {
    16, 11, 10, 16, 24, 40, 51, 61,
    12, 12, 14, 19, 26, 58, 60, 55,
    14, 13, 16, 24, 40, 57, 69, 56,
    14, 17, 22, 29, 51, 87, 80, 62,
    18, 22, 37, 56, 68,109,103, 77,
    24, 35, 55, 64, 81,104,113, 92,
    49, 64, 78, 87,103,121,120,101,
    72, 92, 95, 98,112,100,103, 99 };
__constant__ int CHRi[64] = {
    17, 18, 24, 47, 99, 99, 99, 99,
    18, 21, 26, 66, 99, 99, 99, 99,
    24, 26, 56, 99, 99, 99, 99, 99,
    47, 66, 99, 99, 99, 99, 99, 99,
    99, 99, 99, 99, 99, 99, 99, 99,
    99, 99, 99, 99, 99, 99, 99, 99,
    99, 99, 99, 99, 99, 99, 99, 99,
    99, 99, 99, 99, 99, 99, 99, 99 };

// -------- float2 elementwise helpers (scalar FFMA pairs) --------
__device__ __forceinline__ float2 f2add(float2 a, float2 b){ return make_float2(a.x+b.x, a.y+b.y); }
__device__ __forceinline__ float2 f2sub(float2 a, float2 b){ return make_float2(a.x-b.x, a.y-b.y); }
__device__ __forceinline__ float2 f2scale(float s, float2 a){ return make_float2(s*a.x, s*a.y); }
__device__ __forceinline__ float2 f2fma(float s, float2 a, float2 b){
    return make_float2(fmaf(s,a.x,b.x), fmaf(s,a.y,b.y)); }

// forward 8-pt DCT-II (even/odd factored) on float2 lanes
__device__ __forceinline__ void fwd8(const float2 v[8], float2 c[8])
{
    float2 e0=f2add(v[0],v[7]), e1=f2add(v[1],v[6]), e2=f2add(v[2],v[5]), e3=f2add(v[3],v[4]);
    float2 o0=f2sub(v[0],v[7]), o1=f2sub(v[1],v[6]), o2=f2sub(v[2],v[5]), o3=f2sub(v[3],v[4]);
    float2 s03=f2add(e0,e3), s12=f2add(e1,e2);
    float2 d03=f2sub(e0,e3), d12=f2sub(e1,e2);
    c[0]=f2scale(HC4, f2add(s03,s12));
    c[4]=f2scale(HC4, f2sub(s03,s12));
    c[2]=f2fma(HC2,d03, f2scale( HC6,d12));
    c[6]=f2fma(HC6,d03, f2scale(-HC2,d12));
    c[1]=f2fma(HC1,o0, f2fma( HC3,o1, f2fma( HC5,o2, f2scale( HC7,o3))));
    c[3]=f2fma(HC3,o0, f2fma(-HC7,o1, f2fma(-HC1,o2, f2scale(-HC5,o3))));
    c[5]=f2fma(HC5,o0, f2fma(-HC1,o1, f2fma( HC7,o2, f2scale( HC3,o3))));
    c[7]=f2fma(HC7,o0, f2fma(-HC5,o1, f2fma( HC3,o2, f2scale(-HC1,o3))));
}

// inverse pass (apply D^T) on float2 lanes
__device__ __forceinline__ void inv8(const float2 c[8], float2 out[8])
{
    float2 A=f2scale(HC4, f2add(c[0],c[4]));
    float2 B=f2scale(HC4, f2sub(c[0],c[4]));
    float2 X=f2fma(HC2,c[2], f2scale( HC6,c[6]));
    float2 Y=f2fma(HC6,c[2], f2scale(-HC2,c[6]));
    float2 p0=f2add(A,X), p3=f2sub(A,X);
    float2 p1=f2add(B,Y), p2=f2sub(B,Y);
    float2 m0=f2fma(HC1,c[1], f2fma( HC3,c[3], f2fma( HC5,c[5], f2scale( HC7,c[7]))));
    float2 m1=f2fma(HC3,c[1], f2fma(-HC7,c[3], f2fma(-HC1,c[5], f2scale(-HC5,c[7]))));
    float2 m2=f2fma(HC5,c[1], f2fma(-HC1,c[3], f2fma( HC7,c[5], f2scale( HC3,c[7]))));
    float2 m3=f2fma(HC7,c[1], f2fma(-HC5,c[3], f2fma( HC3,c[5], f2scale(-HC1,c[7]))));
    out[0]=f2add(p0,m0);  out[7]=f2sub(p0,m0);
    out[1]=f2add(p1,m1);  out[6]=f2sub(p1,m1);
    out[2]=f2add(p2,m2);  out[5]=f2sub(p2,m2);
    out[3]=f2add(p3,m3);  out[4]=f2sub(p3,m3);
}

// float2 transpose scratch (units = float2): group stride 88, row stride 10.
// STS.128 writes 4-phase conflict-free; LDS.64 strided reads 2-phase
// conflict-free. Two buffers (ping-pong) per warp.
#define GU2 88
#define RU2 10
#define WBUF2 352

__global__ void __launch_bounds__(256) jpeg_kernel(
    const float* __restrict__ in, const int* __restrict__ quality,
    float* __restrict__ out)
{
    __shared__ float2 tbufA[8][WBUF2];    // 22.5 KB  (stage 1 -> 2)
    __shared__ float2 tbufB[8][WBUF2];    // 22.5 KB  (stage 3 -> 4)
    __shared__ float qT[2][96];           // transposed q: [LUM,CHR][r*12 + i]
    __shared__ float rqT[2][96];          // reciprocals

    const int tid = threadIdx.x;
    const int w = tid >> 5;         // warp 0..7
    const int g = (tid >> 3) & 3;   // group within warp
    const int r = tid & 7;          // row within 8x8 block
    const int p = tid >> 3;         // 0..31: owns blocks p and p+32

    const int rowblk = blockIdx.x & 63;
    const int batch = blockIdx.x >> 6;

    const size_t base = (size_t)batch * 3 * PLANE
                      + (size_t)(rowblk * 8 + r) * W + p * 8;

    // ---- global loads first (latency overlapped with q-table build) ----
    float rv[16], gv[16], bv[16];   // [0..7]=block p, [8..15]=block p+32
    {
        const float* pr = in + base;
        const float* pg = in + base + PLANE;
        const float* pb = in + base + 2 * PLANE;
        *(float4*)&rv[0]  = __ldg((const float4*)pr);
        *(float4*)&rv[4]  = __ldg((const float4*)(pr + 4));
        *(float4*)&rv[8]  = __ldg((const float4*)(pr + 256));
        *(float4*)&rv[12] = __ldg((const float4*)(pr + 260));
        *(float4*)&gv[0]  = __ldg((const float4*)pg);
        *(float4*)&gv[4]  = __ldg((const float4*)(pg + 4));
        *(float4*)&gv[8]  = __ldg((const float4*)(pg + 256));
        *(float4*)&gv[12] = __ldg((const float4*)(pg + 260));
        *(float4*)&bv[0]  = __ldg((const float4*)pb);
        *(float4*)&bv[4]  = __ldg((const float4*)(pb + 4));
        *(float4*)&bv[8]  = __ldg((const float4*)(pb + 256));
        *(float4*)&bv[12] = __ldg((const float4*)(pb + 260));
    }

    // ---- quant tables (2 tables: LUM, CHR): exact int math q>=50 ----
    if (tid < 128) {
        int c = tid >> 6;           // 0 = LUM, 1 = CHR
        int rr = (tid >> 3) & 7;
        int ii = tid & 7;
        int q = quality[0];
        q = max(1, min(100, q));
        int t = (c == 0) ? LUMi[ii * 8 + rr] : CHRi[ii * 8 + rr];
        float s;
        if (q >= 50) {
            int k = (t * (200 - 2 * q) + 50) / 100;
            k = max(1, min(255, k));
            s = (float)k;
        } else {
            double scale = 5000.0 / q;
            double sd = floor(((double)t * scale + 50.0) / 100.0);
            s = (float)fmin(fmax(sd, 1.0), 255.0);
        }
        qT[c][rr * 12 + ii] = s;
        rqT[c][rr * 12 + ii] = __frcp_rn(s);
    }

    // ---- color convert; pack {block p, block p+32} into float2 lanes ----
    float2 ch[3][8];
    #pragma unroll
    for (int e = 0; e < 8; e++) {
        float ra = rintf(rv[e] * 255.f),     rb = rintf(rv[e + 8] * 255.f);
        float ga = rintf(gv[e] * 255.f),     gb = rintf(gv[e + 8] * 255.f);
        float ba = rintf(bv[e] * 255.f),     bb = rintf(bv[e + 8] * 255.f);
        ch[0][e] = make_float2(
            0.299f*ra + 0.587f*ga + 0.114f*ba - 128.f,
            0.299f*rb + 0.587f*gb + 0.114f*bb - 128.f);
        ch[1][e] = make_float2(
            -0.168736f*ra - 0.331264f*ga + 0.5f*ba,
            -0.168736f*rb - 0.331264f*gb + 0.5f*bb);
        ch[2][e] = make_float2(
            0.5f*ra - 0.418688f*ga - 0.081312f*ba,
            0.5f*rb - 0.418688f*gb - 0.081312f*bb);
    }

    __syncthreads();   // publish q tables

    float2* wrA = &tbufA[w][g * GU2 + r * RU2];
    float2* rdA = &tbufA[w][g * GU2 + r];
    float2* wrB = &tbufB[w][g * GU2 + r * RU2];
    float2* rdB = &tbufB[w][g * GU2 + r];

    // loop-carried q registers: loaded at c=0 (LUM) and c=1 (CHR); c=2 reuses.
    float qa[8], sa[8];

    // ---- per-channel pipeline, double-buffered (2 syncwarps per channel) ----
    #pragma unroll
    for (int c = 0; c < 3; c++) {
        // stage 1: row DCT, write rows into A
        float2 t[8];
        fwd8(ch[c], t);
        #pragma unroll
        for (int k = 0; k < 8; k += 2)
            *(float4*)(wrA + k) = make_float4(t[k].x, t[k].y, t[k+1].x, t[k+1].y);

        // refresh q registers (LUM for c=0, CHR for c=1; c=2 reuses CHR)
        if (c < 2) {
            float4 q0 = *(const float4*)&qT[c][r * 12];
            float4 q1 = *(const float4*)&qT[c][r * 12 + 4];
            float4 s0 = *(const float4*)&rqT[c][r * 12];
            float4 s1 = *(const float4*)&rqT[c][r * 12 + 4];
            qa[0]=q0.x; qa[1]=q0.y; qa[2]=q0.z; qa[3]=q0.w;
            qa[4]=q1.x; qa[5]=q1.y; qa[6]=q1.z; qa[7]=q1.w;
            sa[0]=s0.x; sa[1]=s0.y; sa[2]=s0.z; sa[3]=s0.w;
            sa[4]=s1.x; sa[5]=s1.y; sa[6]=s1.z; sa[7]=s1.w;
        }
        __syncwarp();

        // stage 2: column read from A (8x LDS.64)
        float2 tc[8];
        #pragma unroll
        for (int i = 0; i < 8; i++) tc[i] = rdA[i * RU2];

        // stage 3: column DCT + quantize + column IDCT, write into B
        float2 cc[8];
        fwd8(tc, cc);
        #pragma unroll
        for (int i = 0; i < 8; i++) {
            float y0x = cc[i].x * sa[i];
            float y0y = cc[i].y * sa[i];
            float y1x = fmaf(fmaf(-qa[i], y0x, cc[i].x), sa[i], y0x);
            float y1y = fmaf(fmaf(-qa[i], y0y, cc[i].y), sa[i], y0y);
            cc[i].x = rintf(y1x) * qa[i];
            cc[i].y = rintf(y1y) * qa[i];
        }
        inv8(cc, t);
        #pragma unroll
        for (int k = 0; k < 8; k += 2)
            *(float4*)(wrB + k) = make_float4(t[k].x, t[k].y, t[k+1].x, t[k+1].y);
        __syncwarp();
        // (retires this channel's stage-2 A-reads: next channel's A-writes safe;
        //  the stage-1 syncwarp above retires prev channel's B-reads)

        // stage 4: column read from B, then row IDCT
        #pragma unroll
        for (int i = 0; i < 8; i++) tc[i] = rdB[i * RU2];
        inv8(tc, ch[c]);
    }

    // ---- color back-convert + clamp + round + /255, streaming stores ----
    const float inv255 = 1.0f / 255.0f;
    float R[16], G[16], B2[16];
    #pragma unroll
    for (int e = 0; e < 8; e++) {
        #pragma unroll
        for (int h = 0; h < 2; h++) {
            float yy = (h ? ch[0][e].y : ch[0][e].x) + 128.f;
            float cb =  h ? ch[1][e].y : ch[1][e].x;
            float cr =  h ? ch[2][e].y : ch[2][e].x;
            float rr = fmaf(1.402f, cr, yy);
            float gg = fmaf(-0.344136f, cb, fmaf(-0.714136f, cr, yy));
            float bb = fmaf(1.772f, cb, yy);
            int o = e + 8 * h;
            R[o]  = rintf(fminf(fmaxf(rr, 0.f), 255.f)) * inv255;
            G[o]  = rintf(fminf(fmaxf(gg, 0.f), 255.f)) * inv255;
            B2[o] = rintf(fminf(fmaxf(bb, 0.f), 255.f)) * inv255;
        }
    }
    float* qr = out + base;
    float* qg = out + base + PLANE;
    float* qb = out + base + 2 * PLANE;
    __stcs((float4*)qr,         *(float4*)&R[0]);
    __stcs((float4*)(qr + 4),   *(float4*)&R[4]);
    __stcs((float4*)(qr + 256), *(float4*)&R[8]);
    __stcs((float4*)(qr + 260), *(float4*)&R[12]);
    __stcs((float4*)qg,         *(float4*)&G[0]);
    __stcs((float4*)(qg + 4),   *(float4*)&G[4]);
    __stcs((float4*)(qg + 256), *(float4*)&G[8]);
    __stcs((float4*)(qg + 260), *(float4*)&G[12]);
    __stcs((float4*)qb,         *(float4*)&B2[0]);
    __stcs((float4*)(qb + 4),   *(float4*)&B2[4]);
    __stcs((float4*)(qb + 256), *(float4*)&B2[8]);
    __stcs((float4*)(qb + 260), *(float4*)&B2[12]);
}

extern "C" void kernel_launch(void* const* d_in, const int* in_sizes, int n_in,
                              void* d_out, int out_size)
{
    const float* in = (const float*)d_in[0];
    const int* quality = (const int*)d_in[1];
    if (n_in >= 2 && in_sizes[0] == 1) {   // defensive: swap if order reversed
        quality = (const int*)d_in[0];
        in = (const float*)d_in[1];
    }
    float* out = (float*)d_out;

    const int nCTA = 32 * 64;              // batch * block-rows (full-width strips)
    jpeg_kernel<<<nCTA, 256>>>(in, quality, out);
}

// round 12
// speedup vs baseline: 1.0349x; 1.0349x over previous
#include <cuda_runtime.h>
#include <math.h>

#define W 512
#define H 512
#define PLANE (W * H)

// hcK = 0.5 * cos(K*pi/16), float32 of the exact float64 values
#define HC1 0.4903926402016152f
#define HC2 0.4619397662556434f
#define HC3 0.4157348061512726f
#define HC4 0.3535533905932738f
#define HC5 0.2777851165098011f
#define HC6 0.1913417161825449f
#define HC7 0.0975451610080641f

__constant__ int LUMi[64] = {
    16, 11, 10, 16, 24, 40, 51, 61,
    12, 12, 14, 19, 26, 58, 60, 55,
    14, 13, 16, 24, 40, 57, 69, 56,
    14, 17, 22, 29, 51, 87, 80, 62,
    18, 22, 37, 56, 68,109,103, 77,
    24, 35, 55, 64, 81,104,113, 92,
    49, 64, 78, 87,103,121,120,101,
    72, 92, 95, 98,112,100,103, 99 };
__constant__ int CHRi[64] = {
    17, 18, 24, 47, 99, 99, 99, 99,
    18, 21, 26, 66, 99, 99, 99, 99,
    24, 26, 56, 99, 99, 99, 99, 99,
    47, 66, 99, 99, 99, 99, 99, 99,
    99, 99, 99, 99, 99, 99, 99, 99,
    99, 99, 99, 99, 99, 99, 99, 99,
    99, 99, 99, 99, 99, 99, 99, 99,
    99, 99, 99, 99, 99, 99, 99, 99 };

// -------- float2 elementwise helpers (scalar FFMA pairs) --------
__device__ __forceinline__ float2 f2add(float2 a, float2 b){ return make_float2(a.x+b.x, a.y+b.y); }
__device__ __forceinline__ float2 f2sub(float2 a, float2 b){ return make_float2(a.x-b.x, a.y-b.y); }
__device__ __forceinline__ float2 f2scale(float s, float2 a){ return make_float2(s*a.x, s*a.y); }
__device__ __forceinline__ float2 f2fma(float s, float2 a, float2 b){
    return make_float2(fmaf(s,a.x,b.x), fmaf(s,a.y,b.y)); }

// forward 8-pt DCT-II (even/odd factored) on float2 lanes
__device__ __forceinline__ void fwd8(const float2 v[8], float2 c[8])
{
    float2 e0=f2add(v[0],v[7]), e1=f2add(v[1],v[6]), e2=f2add(v[2],v[5]), e3=f2add(v[3],v[4]);
    float2 o0=f2sub(v[0],v[7]), o1=f2sub(v[1],v[6]), o2=f2sub(v[2],v[5]), o3=f2sub(v[3],v[4]);
    float2 s03=f2add(e0,e3), s12=f2add(e1,e2);
    float2 d03=f2sub(e0,e3), d12=f2sub(e1,e2);
    c[0]=f2scale(HC4, f2add(s03,s12));
    c[4]=f2scale(HC4, f2sub(s03,s12));
    c[2]=f2fma(HC2,d03, f2scale( HC6,d12));
    c[6]=f2fma(HC6,d03, f2scale(-HC2,d12));
    c[1]=f2fma(HC1,o0, f2fma( HC3,o1, f2fma( HC5,o2, f2scale( HC7,o3))));
    c[3]=f2fma(HC3,o0, f2fma(-HC7,o1, f2fma(-HC1,o2, f2scale(-HC5,o3))));
    c[5]=f2fma(HC5,o0, f2fma(-HC1,o1, f2fma( HC7,o2, f2scale( HC3,o3))));
    c[7]=f2fma(HC7,o0, f2fma(-HC5,o1, f2fma( HC3,o2, f2scale(-HC1,o3))));
}

// inverse pass (apply D^T) on float2 lanes
__device__ __forceinline__ void inv8(const float2 c[8], float2 out[8])
{
    float2 A=f2scale(HC4, f2add(c[0],c[4]));
    float2 B=f2scale(HC4, f2sub(c[0],c[4]));
    float2 X=f2fma(HC2,c[2], f2scale( HC6,c[6]));
    float2 Y=f2fma(HC6,c[2], f2scale(-HC2,c[6]));
    float2 p0=f2add(A,X), p3=f2sub(A,X);
    float2 p1=f2add(B,Y), p2=f2sub(B,Y);
    float2 m0=f2fma(HC1,c[1], f2fma( HC3,c[3], f2fma( HC5,c[5], f2scale( HC7,c[7]))));
    float2 m1=f2fma(HC3,c[1], f2fma(-HC7,c[3], f2fma(-HC1,c[5], f2scale(-HC5,c[7]))));
    float2 m2=f2fma(HC5,c[1], f2fma(-HC1,c[3], f2fma( HC7,c[5], f2scale( HC3,c[7]))));
    float2 m3=f2fma(HC7,c[1], f2fma(-HC5,c[3], f2fma( HC3,c[5], f2scale(-HC1,c[7]))));
    out[0]=f2add(p0,m0);  out[7]=f2sub(p0,m0);
    out[1]=f2add(p1,m1);  out[6]=f2sub(p1,m1);
    out[2]=f2add(p2,m2);  out[5]=f2sub(p2,m2);
    out[3]=f2add(p3,m3);  out[4]=f2sub(p3,m3);
}

// float2 transpose scratch (units = float2): group stride 88, row stride 10.
// STS.128 writes 4-phase conflict-free; LDS.64 strided reads 2-phase
// conflict-free (group bank offset 16g per half-warp phase).
#define GU2 88
#define RU2 10
#define WBUF2 352

__global__ void __launch_bounds__(256) jpeg_kernel(
    const float* __restrict__ in, const int* __restrict__ quality,
    float* __restrict__ out)
{
    __shared__ float2 tbuf[8][WBUF2];     // 22.5 KB, reused per channel
    __shared__ float qT[3][96];           // transposed q:  [c][r*12 + i]
    __shared__ float rqT[3][96];          // reciprocals

    const int tid = threadIdx.x;
    const int w = tid >> 5;         // warp 0..7
    const int g = (tid >> 3) & 3;   // group within warp
    const int r = tid & 7;          // row within 8x8 block
    const int p = tid >> 3;         // 0..31: owns blocks p and p+32

    const int rowblk = blockIdx.x & 63;
    const int batch = blockIdx.x >> 6;

    const size_t base = (size_t)batch * 3 * PLANE
                      + (size_t)(rowblk * 8 + r) * W + p * 8;

    // ---- global loads first (latency overlapped with q-table build) ----
    float rv[16], gv[16], bv[16];   // [0..7]=block p, [8..15]=block p+32
    {
        const float* pr = in + base;
        const float* pg = in + base + PLANE;
        const float* pb = in + base + 2 * PLANE;
        *(float4*)&rv[0]  = __ldg((const float4*)pr);
        *(float4*)&rv[4]  = __ldg((const float4*)(pr + 4));
        *(float4*)&rv[8]  = __ldg((const float4*)(pr + 256));
        *(float4*)&rv[12] = __ldg((const float4*)(pr + 260));
        *(float4*)&gv[0]  = __ldg((const float4*)pg);
        *(float4*)&gv[4]  = __ldg((const float4*)(pg + 4));
        *(float4*)&gv[8]  = __ldg((const float4*)(pg + 256));
        *(float4*)&gv[12] = __ldg((const float4*)(pg + 260));
        *(float4*)&bv[0]  = __ldg((const float4*)pb);
        *(float4*)&bv[4]  = __ldg((const float4*)(pb + 4));
        *(float4*)&bv[8]  = __ldg((const float4*)(pb + 256));
        *(float4*)&bv[12] = __ldg((const float4*)(pb + 260));
    }

    // ---- quant tables: exact int math q>=50, DP only cold branch ----
    if (tid < 192) {
        int c = tid >> 6;
        int rr = (tid >> 3) & 7;
        int ii = tid & 7;
        int q = quality[0];
        q = max(1, min(100, q));
        int t = (c == 0) ? LUMi[ii * 8 + rr] : CHRi[ii * 8 + rr];
        float s;
        if (q >= 50) {
            int k = (t * (200 - 2 * q) + 50) / 100;
            k = max(1, min(255, k));
            s = (float)k;
        } else {
            double scale = 5000.0 / q;
            double sd = floor(((double)t * scale + 50.0) / 100.0);
            s = (float)fmin(fmax(sd, 1.0), 255.0);
        }
        qT[c][rr * 12 + ii] = s;
        rqT[c][rr * 12 + ii] = __frcp_rn(s);
    }

    // ---- color convert; pack {block p, block p+32} into float2 lanes ----
    float2 ch[3][8];
    #pragma unroll
    for (int e = 0; e < 8; e++) {
        float ra = rintf(rv[e] * 255.f),     rb = rintf(rv[e + 8] * 255.f);
        float ga = rintf(gv[e] * 255.f),     gb = rintf(gv[e + 8] * 255.f);
        float ba = rintf(bv[e] * 255.f),     bb = rintf(bv[e + 8] * 255.f);
        ch[0][e] = make_float2(
            0.299f*ra + 0.587f*ga + 0.114f*ba - 128.f,
            0.299f*rb + 0.587f*gb + 0.114f*bb - 128.f);
        ch[1][e] = make_float2(
            -0.168736f*ra - 0.331264f*ga + 0.5f*ba,
            -0.168736f*rb - 0.331264f*gb + 0.5f*bb);
        ch[2][e] = make_float2(
            0.5f*ra - 0.418688f*ga - 0.081312f*ba,
            0.5f*rb - 0.418688f*gb - 0.081312f*bb);
    }

    __syncthreads();   // publish q tables

    float2* wrb = &tbuf[w][g * GU2 + r * RU2];   // write base
    float2* rdb = &tbuf[w][g * GU2 + r];         // read base (column r)

    // ---- per-channel pipeline through the shared transpose buffer ----
    #pragma unroll
    for (int c = 0; c < 3; c++) {
        // stage 1: row DCT, write rows (4x STS.128)
        float2 t[8];
        fwd8(ch[c], t);
        #pragma unroll
        for (int k = 0; k < 8; k += 2)
            *(float4*)(wrb + k) = make_float4(t[k].x, t[k].y, t[k+1].x, t[k+1].y);
        __syncwarp();

        // stage 2: column read (8x LDS.64)
        float2 tc[8];
        #pragma unroll
        for (int i = 0; i < 8; i++) tc[i] = rdb[i * RU2];
        __syncwarp();                       // reads done before overwrite

        // stage 3: column DCT + quantize + column IDCT
        float2 cc[8];
        fwd8(tc, cc);
        float4 q0 = *(const float4*)&qT[c][r * 12];
        float4 q1 = *(const float4*)&qT[c][r * 12 + 4];
        float4 s0 = *(const float4*)&rqT[c][r * 12];
        float4 s1 = *(const float4*)&rqT[c][r * 12 + 4];
        float qa[8] = { q0.x,q0.y,q0.z,q0.w, q1.x,q1.y,q1.z,q1.w };
        float sa[8] = { s0.x,s0.y,s0.z,s0.w, s1.x,s1.y,s1.z,s1.w };
        #pragma unroll
        for (int i = 0; i < 8; i++) {
            float y0x = cc[i].x * sa[i];
            float y0y = cc[i].y * sa[i];
            float y1x = fmaf(fmaf(-qa[i], y0x, cc[i].x), sa[i], y0x);
            float y1y = fmaf(fmaf(-qa[i], y0y, cc[i].y), sa[i], y0y);
            cc[i].x = rintf(y1x) * qa[i];
            cc[i].y = rintf(y1y) * qa[i];
        }
        inv8(cc, t);
        #pragma unroll
        for (int k = 0; k < 8; k += 2)
            *(float4*)(wrb + k) = make_float4(t[k].x, t[k].y, t[k+1].x, t[k+1].y);
        __syncwarp();

        // stage 4: column read back to rows
        #pragma unroll
        for (int i = 0; i < 8; i++) tc[i] = rdb[i * RU2];
        __syncwarp();                       // before next channel's writes

        // stage 5: row IDCT, back into registers
        inv8(tc, ch[c]);
    }

    // ---- color back-convert + clamp + round + /255, streaming stores ----
    const float inv255 = 1.0f / 255.0f;
    float R[16], G[16], B2[16];
    #pragma unroll
    for (int e = 0; e < 8; e++) {
        #pragma unroll
        for (int h = 0; h < 2; h++) {
            float yy = (h ? ch[0][e].y : ch[0][e].x) + 128.f;
            float cb =  h ? ch[1][e].y : ch[1][e].x;
            float cr =  h ? ch[2][e].y : ch[2][e].x;
            float rr = fmaf(1.402f, cr, yy);
            float gg = fmaf(-0.344136f, cb, fmaf(-0.714136f, cr, yy));
            float bb = fmaf(1.772f, cb, yy);
            int o = e + 8 * h;
            R[o]  = rintf(fminf(fmaxf(rr, 0.f), 255.f)) * inv255;
            G[o]  = rintf(fminf(fmaxf(gg, 0.f), 255.f)) * inv255;
            B2[o] = rintf(fminf(fmaxf(bb, 0.f), 255.f)) * inv255;
        }
    }
    float* qr = out + base;
    float* qg = out + base + PLANE;
    float* qb = out + base + 2 * PLANE;
    __stcs((float4*)qr,         *(float4*)&R[0]);
    __stcs((float4*)(qr + 4),   *(float4*)&R[4]);
    __stcs((float4*)(qr + 256), *(float4*)&R[8]);
    __stcs((float4*)(qr + 260), *(float4*)&R[12]);
    __stcs((float4*)qg,         *(float4*)&G[0]);
    __stcs((float4*)(qg + 4),   *(float4*)&G[4]);
    __stcs((float4*)(qg + 256), *(float4*)&G[8]);
    __stcs((float4*)(qg + 260), *(float4*)&G[12]);
    __stcs((float4*)qb,         *(float4*)&B2[0]);
    __stcs((float4*)(qb + 4),   *(float4*)&B2[4]);
    __stcs((float4*)(qb + 256), *(float4*)&B2[8]);
    __stcs((float4*)(qb + 260), *(float4*)&B2[12]);
}

extern "C" void kernel_launch(void* const* d_in, const int* in_sizes, int n_in,
                              void* d_out, int out_size)
{
    const float* in = (const float*)d_in[0];
    const int* quality = (const int*)d_in[1];
    if (n_in >= 2 && in_sizes[0] == 1) {   // defensive: swap if order reversed
        quality = (const int*)d_in[0];
        in = (const float*)d_in[1];
    }
    float* out = (float*)d_out;

    const int nCTA = 32 * 64;              // batch * block-rows (full-width strips)
    jpeg_kernel<<<nCTA, 256>>>(in, quality, out);
}